// round 1
// baseline (speedup 1.0000x reference)
#include <cuda_runtime.h>
#include <math.h>

#define NEG_K 32
#define TEMP 0.07f

// d_out init: zero rows (l >= loss_size) each contribute -log_softmax(0-vector)[0] = log(33).
// Sum over 'valid_size' such rows, divided by B.
__global__ void infonce_init_kernel(const int* __restrict__ vs, float* __restrict__ out, int B) {
    int valid = vs[0];
    out[0] = (float)valid * logf((float)(NEG_K + 1)) / (float)B;
}

__global__ __launch_bounds__(256) void infonce_kernel(
    const float* __restrict__ hs,       // [B, S, H]
    const int*   __restrict__ selection,// [B]
    const int*   __restrict__ mask,     // [B, S]
    const float* __restrict__ noise,    // [loss_size, NEG_K]
    const int*   __restrict__ vs,       // [1] valid_size
    float* __restrict__ out,            // [1]
    int B, int S, int H)
{
    const int l = blockIdx.x;
    const int valid = vs[0];
    const int loss_size = B - valid;
    if (l >= loss_size) return;

    const int tid  = threadIdx.x;
    const int lane = tid & 31;
    const int warp = tid >> 5;
    const int nwarps = blockDim.x >> 5;

    extern __shared__ float smem[];
    float* anchor_s = smem;               // H floats
    float* logits_s = smem + H;           // NEG_K+1 floats
    int*   cand_s   = (int*)(logits_s + (NEG_K + 1)); // NEG_K ints
    __shared__ int wsum[8];
    __shared__ int length_s;

    // --- 1. length = sum(mask[l, :]) ---
    int ls = 0;
    for (int s = tid; s < S; s += blockDim.x) ls += mask[(size_t)l * S + s];
    #pragma unroll
    for (int o = 16; o; o >>= 1) ls += __shfl_xor_sync(0xffffffffu, ls, o);
    if (lane == 0) wsum[warp] = ls;
    __syncthreads();
    if (tid == 0) {
        int tot = 0;
        for (int w = 0; w < nwarps; w++) tot += wsum[w];
        length_s = tot;
    }
    __syncthreads();

    const int len_l = length_s;
    const int sel = selection[l];
    const bool sel_in_range = (sel >= 1) && (sel <= len_l - 1);
    const int n_valid = sel_in_range ? (len_l - 2) : (len_l - 1);

    // --- 2. candidate negative indices (threads 0..NEG_K-1) ---
    if (tid < NEG_K) {
        float nv = (float)n_valid;
        int u = (int)floorf(noise[(size_t)l * NEG_K + tid] * nv);
        int cand = u + 1;
        if (sel_in_range && cand >= sel) cand += 1;
        cand_s[tid] = cand;
    }

    // --- 3. stage anchor into shared (float4) ---
    const int H4 = H >> 2;
    const float4* __restrict__ anc_g = (const float4*)(hs + ((size_t)l * S + sel) * H);
    float4* anc_s4 = (float4*)anchor_s;
    for (int i = tid; i < H4; i += blockDim.x) anc_s4[i] = anc_g[i];
    __syncthreads();

    // --- 4. 33 dot products, one per warp round-robin ---
    const float4* a4 = (const float4*)anchor_s;
    for (int j = warp; j <= NEG_K; j += nwarps) {
        const float* vptr;
        if (j == 0) {
            vptr = hs + ((size_t)(valid + l) * S + sel) * H;     // positive
        } else {
            vptr = hs + ((size_t)l * S + cand_s[j - 1]) * H;     // negative j-1
        }
        const float4* v4 = (const float4*)vptr;
        float acc = 0.0f;
        #pragma unroll 6
        for (int i = lane; i < H4; i += 32) {
            float4 a = a4[i];
            float4 b = v4[i];
            acc += a.x * b.x + a.y * b.y + a.z * b.z + a.w * b.w;
        }
        #pragma unroll
        for (int o = 16; o; o >>= 1) acc += __shfl_xor_sync(0xffffffffu, acc, o);
        if (lane == 0) logits_s[j] = acc;
    }
    __syncthreads();

    // --- 5. per-row loss: -(logit0/T - logsumexp(logits/T)) ---
    if (tid == 0) {
        float m = -INFINITY;
        #pragma unroll
        for (int j = 0; j <= NEG_K; j++) {
            float li = logits_s[j] / TEMP;
            m = fmaxf(m, li);
        }
        float ssum = 0.0f;
        #pragma unroll
        for (int j = 0; j <= NEG_K; j++) {
            float li = logits_s[j] / TEMP;
            ssum += expf(li - m);
        }
        float lse = m + logf(ssum);
        float rowloss = lse - logits_s[0] / TEMP;
        atomicAdd(out, rowloss / (float)B);
    }
}

extern "C" void kernel_launch(void* const* d_in, const int* in_sizes, int n_in,
                              void* d_out, int out_size) {
    const float* hs        = (const float*)d_in[0]; // hidden_states [B,S,H]
    const int*   selection = (const int*)  d_in[1]; // [B]
    const int*   mask      = (const int*)  d_in[2]; // [B,S]
    const float* noise     = (const float*)d_in[3]; // [loss_size, NEG_K]
    const int*   vs        = (const int*)  d_in[4]; // [1] valid_size
    float*       out       = (float*)d_out;

    const int B = in_sizes[1];
    const int S = in_sizes[2] / B;
    const int H = in_sizes[0] / (B * S);

    infonce_init_kernel<<<1, 1>>>(vs, out, B);

    size_t shmem = (size_t)H * sizeof(float) + (NEG_K + 1) * sizeof(float) + NEG_K * sizeof(int);
    infonce_kernel<<<B, 256, shmem>>>(hs, selection, mask, noise, vs, out, B, S, H);
}

// round 4
// speedup vs baseline: 1.1345x; 1.1345x over previous
#include <cuda_runtime.h>
#include <math.h>

#define NEG_K 32
#define TEMP 0.07f

// Self-resetting cross-block accumulator (zero-initialized; last block resets).
__device__ float g_sum;
__device__ int   g_count;

__global__ __launch_bounds__(256) void infonce_kernel(
    const float* __restrict__ hs,       // [B, S, H]
    const int*   __restrict__ selection,// [B]
    const int*   __restrict__ mask,     // [B, S]
    const float* __restrict__ noise,    // [loss_size, NEG_K]
    float* __restrict__ out,            // [1]
    int B, int S, int H, int valid)     // valid = B - loss_size (host-computed)
{
    const int l    = blockIdx.x;        // grid = loss_size exactly
    const int tid  = threadIdx.x;
    const int lane = tid & 31;
    const int warp = tid >> 5;

    extern __shared__ float smem[];
    float* anchor_s = smem;                              // H floats
    float* logits_s = smem + H;                          // NEG_K+1
    int*   cand_s   = (int*)(logits_s + (NEG_K + 1));    // NEG_K

    const int sel = selection[l];       // uniform broadcast load

    // ---- warp 0: mask-sum -> length -> candidate indices (needs noise) ----
    if (warp == 0) {
        // noise for this row (1 per lane)
        float nz = noise[(size_t)l * NEG_K + lane];
        // mask sum: 256 ints, 8 per lane, coalesced
        int msum = 0;
        const int* mrow = mask + (size_t)l * S;
        #pragma unroll 8
        for (int s = lane; s < S; s += 32) msum += mrow[s];
        #pragma unroll
        for (int o = 16; o; o >>= 1) msum += __shfl_xor_sync(0xffffffffu, msum, o);
        const int len_l = msum;  // uniform across warp after reduce

        const bool sel_in_range = (sel >= 1) && (sel <= len_l - 1);
        const int n_valid = sel_in_range ? (len_l - 2) : (len_l - 1);
        int u = (int)floorf(nz * (float)n_valid);
        int cand = u + 1;
        if (sel_in_range && cand >= sel) cand += 1;
        cand_s[lane] = cand;
    } else {
        // ---- warps 1..7: stage anchor into shared (192 float4, 224 lanes) ----
        const int H4 = H >> 2;
        const float4* __restrict__ anc_g = (const float4*)(hs + ((size_t)l * S + sel) * H);
        float4* anc_s4 = (float4*)anchor_s;
        int i = tid - 32;
        if (i < H4) anc_s4[i] = anc_g[i];
    }
    __syncthreads();

    // ---- 33 dot products, TWO per warp concurrently (12 LDG.128 in flight) ----
    const int H4 = H >> 2;
    const float4* a4 = (const float4*)anchor_s;
    const float4* pos4 = (const float4*)(hs + ((size_t)(valid + l) * S + sel) * H);

    for (int j0 = warp; j0 <= NEG_K; j0 += 16) {
        const int j1 = j0 + 8;
        const bool has2 = (j1 <= NEG_K);
        const float4* p0 = (j0 == 0) ? pos4
                         : (const float4*)(hs + ((size_t)l * S + cand_s[j0 - 1]) * H);
        const float4* p1 = has2
                         ? ((j1 == 0) ? pos4
                            : (const float4*)(hs + ((size_t)l * S + cand_s[j1 - 1]) * H))
                         : p0;  // duplicate -> L1 hits, keeps code uniform
        float acc0 = 0.0f, acc1 = 0.0f;
        #pragma unroll 6
        for (int i = lane; i < H4; i += 32) {
            float4 a = a4[i];
            float4 b0 = p0[i];
            float4 b1 = p1[i];
            acc0 += a.x * b0.x + a.y * b0.y + a.z * b0.z + a.w * b0.w;
            acc1 += a.x * b1.x + a.y * b1.y + a.z * b1.z + a.w * b1.w;
        }
        #pragma unroll
        for (int o = 16; o; o >>= 1) {
            acc0 += __shfl_xor_sync(0xffffffffu, acc0, o);
            acc1 += __shfl_xor_sync(0xffffffffu, acc1, o);
        }
        if (lane == 0) {
            logits_s[j0] = acc0;
            if (has2) logits_s[j1] = acc1;
        }
    }
    __syncthreads();

    // ---- per-row loss + grid reduction ----
    if (tid == 0) {
        float m = -INFINITY;
        #pragma unroll
        for (int j = 0; j <= NEG_K; j++) m = fmaxf(m, logits_s[j] * (1.0f / TEMP));
        float ssum = 0.0f;
        #pragma unroll
        for (int j = 0; j <= NEG_K; j++) ssum += __expf(logits_s[j] * (1.0f / TEMP) - m);
        float rowloss = (m + logf(ssum)) - logits_s[0] * (1.0f / TEMP);

        atomicAdd(&g_sum, rowloss);
        __threadfence();
        int done = atomicAdd(&g_count, 1);
        if (done == gridDim.x - 1) {
            float total = atomicExch(&g_sum, 0.0f);   // read + reset for next replay
            g_count = 0;
            out[0] = (total + (float)valid * logf((float)(NEG_K + 1))) / (float)B;
        }
    }
}

extern "C" void kernel_launch(void* const* d_in, const int* in_sizes, int n_in,
                              void* d_out, int out_size) {
    const float* hs        = (const float*)d_in[0]; // [B,S,H]
    const int*   selection = (const int*)  d_in[1]; // [B]
    const int*   mask      = (const int*)  d_in[2]; // [B,S]
    const float* noise     = (const float*)d_in[3]; // [loss_size, NEG_K]
    float*       out       = (float*)d_out;

    const int B = in_sizes[1];
    const int S = in_sizes[2] / B;
    const int H = in_sizes[0] / (B * S);
    const int loss_size = in_sizes[3] / NEG_K;      // host-side: noise shape
    const int valid = B - loss_size;

    size_t shmem = (size_t)H * sizeof(float) + (NEG_K + 1) * sizeof(float) + NEG_K * sizeof(int);
    infonce_kernel<<<loss_size, 256, shmem>>>(hs, selection, mask, noise, out, B, S, H, valid);
}

// round 7
// speedup vs baseline: 1.1629x; 1.0251x over previous
#include <cuda_runtime.h>
#include <math.h>

#define NEG_K 32
#define TEMP 0.07f
#define INV_T (1.0f / 0.07f)

// Self-resetting cross-block accumulator (zero-initialized; last block resets).
__device__ float g_sum;
__device__ int   g_count;

__global__ __launch_bounds__(256, 4) void infonce_kernel(
    const float* __restrict__ hs,       // [B, S, H]
    const int*   __restrict__ selection,// [B]
    const int*   __restrict__ mask,     // [B, S]
    const float* __restrict__ noise,    // [loss_size, NEG_K]
    float* __restrict__ out,            // [1]
    int B, int S, int H, int valid)
{
    const int l    = blockIdx.x;        // grid = loss_size
    const int tid  = threadIdx.x;
    const int lane = tid & 31;
    const int warp = tid >> 5;

    __shared__ float logits_s[NEG_K + 1];

    const int sel = __ldg(selection + l);   // uniform

    // Stream assignment: warp0 -> j=0..4 (5 streams incl. positive),
    // warp w>=1 -> j=4w+1..4w+4 (4 streams). Covers j=0..32.
    const int jbase = (warp == 0) ? 0 : (4 * warp + 1);
    const int cnt   = (warp == 0) ? 5 : 4;

    // Issue per-warp noise loads immediately (lanes 0..cnt-1, negatives only)
    float nz = 0.0f;
    {
        int nj = jbase + lane;
        if (lane < cnt && nj >= 1)
            nz = __ldg(noise + (size_t)l * NEG_K + (nj - 1));
    }

    // Per-warp mask sum (redundant across warps; L1/L2 hits after first)
    int msum = 0;
    {
        const int* mrow = mask + (size_t)l * S;
        #pragma unroll 8
        for (int s = lane; s < S; s += 32) msum += mrow[s];
        #pragma unroll
        for (int o = 16; o; o >>= 1) msum += __shfl_xor_sync(0xffffffffu, msum, o);
    }
    const int len_l = msum;
    const bool sir = (sel >= 1) && (sel <= len_l - 1);
    const int n_valid = sir ? (len_l - 2) : (len_l - 1);

    const int H4 = H >> 2;
    const float4* __restrict__ a4 = (const float4*)(hs + ((size_t)l * S + sel) * H);

    // Build 5 uniform stream pointers (unused streams alias the anchor -> L1 hits)
    const float4* bp[5];
    #pragma unroll
    for (int s = 0; s < 5; s++) {
        const int j = jbase + s;
        const float4* p;
        if (s >= cnt || j > NEG_K) {
            p = a4;
        } else if (j == 0) {
            p = (const float4*)(hs + ((size_t)(valid + l) * S + sel) * H);  // positive
        } else {
            float nzs = __shfl_sync(0xffffffffu, nz, s);
            int cand = (int)floorf(nzs * (float)n_valid) + 1;
            if (sir && cand >= sel) cand += 1;
            p = (const float4*)(hs + ((size_t)l * S + cand) * H);
        }
        bp[s] = p;
    }

    // Single gather round: 5 concurrent dot streams + anchor (direct gmem)
    float acc0 = 0.f, acc1 = 0.f, acc2 = 0.f, acc3 = 0.f, acc4 = 0.f;
    #pragma unroll 6
    for (int i = lane; i < H4; i += 32) {
        float4 a  = a4[i];
        float4 b0 = bp[0][i];
        float4 b1 = bp[1][i];
        float4 b2 = bp[2][i];
        float4 b3 = bp[3][i];
        float4 b4 = bp[4][i];
        acc0 += a.x*b0.x + a.y*b0.y + a.z*b0.z + a.w*b0.w;
        acc1 += a.x*b1.x + a.y*b1.y + a.z*b1.z + a.w*b1.w;
        acc2 += a.x*b2.x + a.y*b2.y + a.z*b2.z + a.w*b2.w;
        acc3 += a.x*b3.x + a.y*b3.y + a.z*b3.z + a.w*b3.w;
        acc4 += a.x*b4.x + a.y*b4.y + a.z*b4.z + a.w*b4.w;
    }
    #pragma unroll
    for (int o = 16; o; o >>= 1) {
        acc0 += __shfl_xor_sync(0xffffffffu, acc0, o);
        acc1 += __shfl_xor_sync(0xffffffffu, acc1, o);
        acc2 += __shfl_xor_sync(0xffffffffu, acc2, o);
        acc3 += __shfl_xor_sync(0xffffffffu, acc3, o);
        acc4 += __shfl_xor_sync(0xffffffffu, acc4, o);
    }
    if (lane == 0) {
        float accs[5] = {acc0, acc1, acc2, acc3, acc4};
        #pragma unroll
        for (int s = 0; s < 5; s++) {
            int j = jbase + s;
            if (s < cnt && j <= NEG_K) logits_s[j] = accs[s];
        }
    }
    __syncthreads();

    // Warp 0: parallel logsumexp over 33 logits
    if (warp == 0) {
        float v = logits_s[lane] * INV_T;
        float e = logits_s[NEG_K] * INV_T;     // j=32, folded at lane 0 only
        float m = (lane == 0) ? fmaxf(v, e) : v;
        #pragma unroll
        for (int o = 16; o; o >>= 1) m = fmaxf(m, __shfl_xor_sync(0xffffffffu, m, o));
        float sse = __expf(v - m);
        if (lane == 0) sse += __expf(e - m);
        #pragma unroll
        for (int o = 16; o; o >>= 1) sse += __shfl_xor_sync(0xffffffffu, sse, o);

        if (lane == 0) {
            float rowloss = (m + logf(sse)) - logits_s[0] * INV_T;
            atomicAdd(&g_sum, rowloss);
            __threadfence();
            int done = atomicAdd(&g_count, 1);
            if (done == gridDim.x - 1) {
                float total = atomicExch(&g_sum, 0.0f);   // reset for graph replay
                g_count = 0;
                out[0] = (total + (float)valid * logf((float)(NEG_K + 1))) / (float)B;
            }
        }
    }
}

extern "C" void kernel_launch(void* const* d_in, const int* in_sizes, int n_in,
                              void* d_out, int out_size) {
    const float* hs        = (const float*)d_in[0]; // [B,S,H]
    const int*   selection = (const int*)  d_in[1]; // [B]
    const int*   mask      = (const int*)  d_in[2]; // [B,S]
    const float* noise     = (const float*)d_in[3]; // [loss_size, NEG_K]
    float*       out       = (float*)d_out;

    const int B = in_sizes[1];
    const int S = in_sizes[2] / B;
    const int H = in_sizes[0] / (B * S);
    const int loss_size = in_sizes[3] / NEG_K;      // from noise shape (host-side)
    const int valid = B - loss_size;

    infonce_kernel<<<loss_size, 256>>>(hs, selection, mask, noise, out, B, S, H, valid);
}